// round 1
// baseline (speedup 1.0000x reference)
#include <cuda_runtime.h>
#include <cuda_bf16.h>

#define NMAX 100000
#define C 256

__device__ float g_H[(size_t)NMAX * C];    // GEMM1 out / GEMM2 out (reused)
__device__ float g_AGG[(size_t)NMAX * C];  // aggregation target
__device__ int   g_deg[NMAX];
__device__ float g_dinv[NMAX];
__device__ int   g_idx64;                  // 1 if edge_index is int64, 0 if int32

// ---------------------------------------------------------------------------
// Edge-index dtype detection: if the buffer is int64 (values < 2^31), every
// odd 32-bit word is zero. With int32 data those words are random indices.
// ---------------------------------------------------------------------------
__global__ void detect_kernel(const void* ei, long n_slots) {
    const int* w = (const int*)ei;
    int tid = threadIdx.x;
    int any = 0;
    long n = n_slots < 2048 ? n_slots : 2048;
    for (long i = tid; i < n; i += blockDim.x)
        if (w[2 * i + 1] != 0) any = 1;
    any = __syncthreads_or(any);
    if (tid == 0) g_idx64 = any ? 0 : 1;
}

__device__ __forceinline__ long fetch_idx(const void* ei, long pos) {
    if (g_idx64)
        return (long)((const long long*)ei)[pos];
    return (long)((const int*)ei)[pos];
}

// ---------------------------------------------------------------------------
// Degree / dinv
// ---------------------------------------------------------------------------
__global__ void zero_deg(int M) {
    int i = blockIdx.x * blockDim.x + threadIdx.x;
    if (i < M) g_deg[i] = 0;
}

__global__ void count_deg(const void* ei, long E) {
    long e = (long)blockIdx.x * blockDim.x + threadIdx.x;
    if (e < E) {
        long col = fetch_idx(ei, E + e);
        atomicAdd(&g_deg[col], 1);
    }
}

__global__ void dinv_kernel(int M) {
    int i = blockIdx.x * blockDim.x + threadIdx.x;
    if (i < M) g_dinv[i] = rsqrtf((float)(g_deg[i] + 1));  // +1 = self loop
}

// ---------------------------------------------------------------------------
// Tiled fp32 GEMM: Out[m,n] = act( A'[m,:] . W[n,:] + bpost[n] )
//   A'[m,k] = PRE ? relu(A[m,k] + bpre[k]) : A[m,k]
// A: [M,256] row-major, W: [256,256] row-major (row n = output channel n).
// Block tile 64x64, K-tile 32, 256 threads, 4x4 microtile.
// ---------------------------------------------------------------------------
template <bool PRE, bool POST>
__global__ void gemm256(const float* __restrict__ A, const float* __restrict__ W,
                        const float* __restrict__ bpre, const float* __restrict__ bpost,
                        float* __restrict__ Out, int M) {
    __shared__ float As[32][68];
    __shared__ float Ws[32][68];

    const int tid = threadIdx.x;
    const int m0 = blockIdx.x * 64;
    const int n0 = blockIdx.y * 64;
    const int ty = tid >> 4;   // 0..15 -> row group
    const int tx = tid & 15;   // 0..15 -> col group

    float acc[4][4] = {};

    for (int k0 = 0; k0 < 256; k0 += 32) {
#pragma unroll
        for (int i = 0; i < 2; i++) {
            int s  = tid + i * 256;   // 0..511
            int r  = s >> 3;          // 0..63
            int c4 = s & 7;           // 0..7
            // A tile (transposed store)
            float4 av = make_float4(0.f, 0.f, 0.f, 0.f);
            int gm = m0 + r;
            if (gm < M)
                av = *(const float4*)(A + (long)gm * 256 + k0 + c4 * 4);
            if (PRE) {
                const float4 bb = *(const float4*)(bpre + k0 + c4 * 4);
                av.x = fmaxf(av.x + bb.x, 0.f);
                av.y = fmaxf(av.y + bb.y, 0.f);
                av.z = fmaxf(av.z + bb.z, 0.f);
                av.w = fmaxf(av.w + bb.w, 0.f);
            }
            As[c4 * 4 + 0][r] = av.x;
            As[c4 * 4 + 1][r] = av.y;
            As[c4 * 4 + 2][r] = av.z;
            As[c4 * 4 + 3][r] = av.w;
            // W tile (transposed store)
            float4 wv = *(const float4*)(W + (long)(n0 + r) * 256 + k0 + c4 * 4);
            Ws[c4 * 4 + 0][r] = wv.x;
            Ws[c4 * 4 + 1][r] = wv.y;
            Ws[c4 * 4 + 2][r] = wv.z;
            Ws[c4 * 4 + 3][r] = wv.w;
        }
        __syncthreads();

#pragma unroll
        for (int k = 0; k < 32; k++) {
            float a[4], b[4];
            *(float4*)a = *(const float4*)&As[k][ty * 4];
            *(float4*)b = *(const float4*)&Ws[k][tx * 4];
#pragma unroll
            for (int i = 0; i < 4; i++)
#pragma unroll
                for (int j = 0; j < 4; j++)
                    acc[i][j] = fmaf(a[i], b[j], acc[i][j]);
        }
        __syncthreads();
    }

#pragma unroll
    for (int i = 0; i < 4; i++) {
        int gm = m0 + ty * 4 + i;
        if (gm >= M) continue;
        float4 v;
        v.x = acc[i][0]; v.y = acc[i][1]; v.z = acc[i][2]; v.w = acc[i][3];
        if (POST) {
            const float4 bb = *(const float4*)(bpost + n0 + tx * 4);
            v.x = fmaxf(v.x + bb.x, 0.f);
            v.y = fmaxf(v.y + bb.y, 0.f);
            v.z = fmaxf(v.z + bb.z, 0.f);
            v.w = fmaxf(v.w + bb.w, 0.f);
        }
        *(float4*)(Out + (long)gm * 256 + n0 + tx * 4) = v;
    }
}

// ---------------------------------------------------------------------------
// Self-loop init: AGG[i,:] = H[i,:] * dinv[i]^2  (also serves as zero-init)
// one float4 per thread
// ---------------------------------------------------------------------------
__global__ void init_agg(int M) {
    long t = (long)blockIdx.x * blockDim.x + threadIdx.x;
    if (t >= (long)M * 64) return;
    long n = t >> 6;
    int  c = (int)(t & 63);
    float s = g_dinv[n];
    s = s * s;
    float4 v = ((const float4*)(g_H + n * 256))[c];
    ((float4*)(g_AGG + n * 256))[c] = make_float4(v.x * s, v.y * s, v.z * s, v.w * s);
}

// ---------------------------------------------------------------------------
// Edge scatter: one warp per edge, vectorized red.global.add.v4.f32
// ---------------------------------------------------------------------------
__global__ void scatter_kernel(const void* ei, long E) {
    long gt   = (long)blockIdx.x * blockDim.x + threadIdx.x;
    long wid  = gt >> 5;
    int  lane = (int)(gt & 31);
    if (wid >= E) return;
    long row = fetch_idx(ei, wid);
    long col = fetch_idx(ei, E + wid);
    float norm = g_dinv[row] * g_dinv[col];
    const float4* src = (const float4*)(g_H + row * 256);
    float4*       dst = (float4*)(g_AGG + col * 256);
#pragma unroll
    for (int i = 0; i < 2; i++) {
        float4 v = src[lane + i * 32];
        asm volatile(
            "red.global.add.v4.f32 [%0], {%1, %2, %3, %4};" ::
            "l"(dst + lane + i * 32),
            "f"(v.x * norm), "f"(v.y * norm), "f"(v.z * norm), "f"(v.w * norm)
            : "memory");
    }
}

// ---------------------------------------------------------------------------
// Final layer: out[n] = sigmoid(relu(dot(H2[n,:], W2) + b2)). One warp/node.
// ---------------------------------------------------------------------------
__global__ void final_kernel(const float* __restrict__ W2, const float* __restrict__ b2,
                             float* __restrict__ out, int M) {
    long gt   = (long)blockIdx.x * blockDim.x + threadIdx.x;
    long w    = gt >> 5;
    int  lane = (int)(gt & 31);
    if (w >= M) return;
    const float4* h  = (const float4*)(g_H + w * 256);
    const float4* wv = (const float4*)W2;
    float s = 0.f;
#pragma unroll
    for (int i = 0; i < 2; i++) {
        float4 a = h[lane + i * 32];
        float4 b = wv[lane + i * 32];
        s = fmaf(a.x, b.x, s);
        s = fmaf(a.y, b.y, s);
        s = fmaf(a.z, b.z, s);
        s = fmaf(a.w, b.w, s);
    }
#pragma unroll
    for (int off = 16; off; off >>= 1)
        s += __shfl_xor_sync(0xFFFFFFFFu, s, off);
    if (lane == 0) {
        float v = fmaxf(s + b2[0], 0.f);
        out[w] = 1.f / (1.f + __expf(-v));
    }
}

// ---------------------------------------------------------------------------
extern "C" void kernel_launch(void* const* d_in, const int* in_sizes, int n_in,
                              void* d_out, int out_size) {
    const float* x     = (const float*)d_in[0];
    const void*  ei    = d_in[1];
    const float* W_gcn = (const float*)d_in[2];
    const float* b_gcn = (const float*)d_in[3];
    const float* W1    = (const float*)d_in[4];
    const float* b1    = (const float*)d_in[5];
    const float* W2    = (const float*)d_in[6];
    const float* b2    = (const float*)d_in[7];
    float* out = (float*)d_out;

    const int  M = in_sizes[0] / C;           // 100000
    const long E = (long)in_sizes[1] / 2;     // 3200000

    float *H, *AGG;
    cudaGetSymbolAddress((void**)&H, g_H);
    cudaGetSymbolAddress((void**)&AGG, g_AGG);

    // 1. detect int32 vs int64 edge indices
    detect_kernel<<<1, 256>>>(ei, E);

    // 2. degrees (targets = edge_index[1]) + self loops -> dinv
    zero_deg<<<(M + 255) / 256, 256>>>(M);
    count_deg<<<(int)((E + 255) / 256), 256>>>(ei, E);
    dinv_kernel<<<(M + 255) / 256, 256>>>(M);

    // 3. H = x @ W_gcn^T
    dim3 ggrid((M + 63) / 64, C / 64);
    gemm256<false, false><<<ggrid, 256>>>(x, W_gcn, nullptr, nullptr, H, M);

    // 4. AGG = H * dinv^2 (self loop + zero init)
    {
        long t = (long)M * 64;
        init_agg<<<(int)((t + 255) / 256), 256>>>(M);
    }

    // 5. edge scatter: AGG[col] += H[row] * dinv[row]*dinv[col]
    {
        long t = E * 32;
        scatter_kernel<<<(int)((t + 255) / 256), 256>>>(ei, E);
    }

    // 6. H = relu( relu(AGG + b_gcn) @ W1^T + b1 )
    gemm256<true, true><<<ggrid, 256>>>(AGG, W1, b_gcn, b1, H, M);

    // 7. out = sigmoid(relu(H @ W2^T + b2))
    {
        long t = (long)M * 32;
        final_kernel<<<(int)((t + 255) / 256), 256>>>(W2, b2, out, M);
    }
}

// round 2
// speedup vs baseline: 1.7305x; 1.7305x over previous
#include <cuda_runtime.h>
#include <cuda_bf16.h>

#define NMAX 100000
#define EMAX 3200000
#define C 256

__device__ float g_H[(size_t)NMAX * C];    // GEMM1 out / GEMM2 out (reused)
__device__ float g_AGG[(size_t)NMAX * C];  // aggregation target
__device__ int   g_deg[NMAX];
__device__ float g_dinv[NMAX];
__device__ int   g_off[NMAX + 1];
__device__ int   g_cursor[NMAX];
__device__ int   g_src[EMAX];
__device__ int   g_bsum[128];
__device__ int   g_bpre[128];
__device__ int   g_idx64;                  // 1 if edge_index is int64, 0 if int32

// ---------------------------------------------------------------------------
// Edge-index dtype detection: int64 values < 2^31 -> every odd 32-bit word 0.
// ---------------------------------------------------------------------------
__global__ void detect_kernel(const void* ei, long n_slots) {
    const int* w = (const int*)ei;
    int tid = threadIdx.x;
    int any = 0;
    long n = n_slots < 2048 ? n_slots : 2048;
    for (long i = tid; i < n; i += blockDim.x)
        if (w[2 * i + 1] != 0) any = 1;
    any = __syncthreads_or(any);
    if (tid == 0) g_idx64 = any ? 0 : 1;
}

__device__ __forceinline__ long fetch_idx(const void* ei, long pos) {
    if (g_idx64)
        return (long)((const long long*)ei)[pos];
    return (long)((const int*)ei)[pos];
}

// ---------------------------------------------------------------------------
// Degree / dinv
// ---------------------------------------------------------------------------
__global__ void zero_deg(int M) {
    int i = blockIdx.x * blockDim.x + threadIdx.x;
    if (i < M) g_deg[i] = 0;
}

__global__ void count_deg(const void* ei, long E) {
    long e = (long)blockIdx.x * blockDim.x + threadIdx.x;
    if (e < E) {
        long col = fetch_idx(ei, E + e);
        atomicAdd(&g_deg[col], 1);
    }
}

__global__ void dinv_kernel(int M) {
    int i = blockIdx.x * blockDim.x + threadIdx.x;
    if (i < M) g_dinv[i] = rsqrtf((float)(g_deg[i] + 1));  // +1 = self loop
}

// ---------------------------------------------------------------------------
// 3-phase exclusive scan of g_deg -> g_off / g_cursor (blocks of 1024)
// ---------------------------------------------------------------------------
__global__ void scan_phase1(int M) {
    __shared__ int s[1024];
    int tid = threadIdx.x;
    int i = blockIdx.x * 1024 + tid;
    s[tid] = (i < M) ? g_deg[i] : 0;
    __syncthreads();
    for (int d = 512; d > 0; d >>= 1) {
        if (tid < d) s[tid] += s[tid + d];
        __syncthreads();
    }
    if (tid == 0) g_bsum[blockIdx.x] = s[0];
}

__global__ void scan_phase2(int nb, int M, int Etot) {
    __shared__ int s[128];
    int tid = threadIdx.x;
    int v = (tid < nb) ? g_bsum[tid] : 0;
    s[tid] = v;
    __syncthreads();
    for (int d = 1; d < 128; d <<= 1) {
        int t = (tid >= d) ? s[tid - d] : 0;
        __syncthreads();
        s[tid] += t;
        __syncthreads();
    }
    if (tid < nb) g_bpre[tid] = s[tid] - v;  // exclusive
    if (tid == 0) g_off[M] = Etot;
}

__global__ void scan_phase3(int M) {
    __shared__ int s[1024];
    int tid = threadIdx.x;
    int i = blockIdx.x * 1024 + tid;
    int v = (i < M) ? g_deg[i] : 0;
    s[tid] = v;
    __syncthreads();
    for (int d = 1; d < 1024; d <<= 1) {
        int t = (tid >= d) ? s[tid - d] : 0;
        __syncthreads();
        s[tid] += t;
        __syncthreads();
    }
    if (i < M) {
        int excl = s[tid] - v + g_bpre[blockIdx.x];
        g_off[i] = excl;
        g_cursor[i] = excl;
    }
}

// ---------------------------------------------------------------------------
// Fill CSR: bucket edges by target col
// ---------------------------------------------------------------------------
__global__ void fill_csr(const void* ei, long E) {
    long e = (long)blockIdx.x * blockDim.x + threadIdx.x;
    if (e < E) {
        int row = (int)fetch_idx(ei, e);
        int col = (int)fetch_idx(ei, E + e);
        int pos = atomicAdd(&g_cursor[col], 1);
        g_src[pos] = row;
    }
}

// ---------------------------------------------------------------------------
// Aggregation: one warp per node. acc = self-loop + sum of incoming messages.
// No atomics; single streaming write of AGG.
// ---------------------------------------------------------------------------
__global__ void agg_kernel(int M) {
    long gt = (long)blockIdx.x * blockDim.x + threadIdx.x;
    int n = (int)(gt >> 5);
    int lane = (int)(gt & 31);
    if (n >= M) return;

    const float4* H4 = (const float4*)g_H;
    float dn = g_dinv[n];
    float sl = dn * dn;

    float4 a0 = H4[(long)n * 64 + lane];
    float4 a1 = H4[(long)n * 64 + 32 + lane];
    float4 acc0 = make_float4(a0.x * sl, a0.y * sl, a0.z * sl, a0.w * sl);
    float4 acc1 = make_float4(a1.x * sl, a1.y * sl, a1.z * sl, a1.w * sl);

    int i = g_off[n];
    int end = g_off[n + 1];
    // 2-edge unrolled for MLP
    for (; i + 1 < end; i += 2) {
        int r0 = g_src[i];
        int r1 = g_src[i + 1];
        float nm0 = dn * g_dinv[r0];
        float nm1 = dn * g_dinv[r1];
        float4 v00 = H4[(long)r0 * 64 + lane];
        float4 v01 = H4[(long)r0 * 64 + 32 + lane];
        float4 v10 = H4[(long)r1 * 64 + lane];
        float4 v11 = H4[(long)r1 * 64 + 32 + lane];
        acc0.x = fmaf(v00.x, nm0, acc0.x); acc0.y = fmaf(v00.y, nm0, acc0.y);
        acc0.z = fmaf(v00.z, nm0, acc0.z); acc0.w = fmaf(v00.w, nm0, acc0.w);
        acc1.x = fmaf(v01.x, nm0, acc1.x); acc1.y = fmaf(v01.y, nm0, acc1.y);
        acc1.z = fmaf(v01.z, nm0, acc1.z); acc1.w = fmaf(v01.w, nm0, acc1.w);
        acc0.x = fmaf(v10.x, nm1, acc0.x); acc0.y = fmaf(v10.y, nm1, acc0.y);
        acc0.z = fmaf(v10.z, nm1, acc0.z); acc0.w = fmaf(v10.w, nm1, acc0.w);
        acc1.x = fmaf(v11.x, nm1, acc1.x); acc1.y = fmaf(v11.y, nm1, acc1.y);
        acc1.z = fmaf(v11.z, nm1, acc1.z); acc1.w = fmaf(v11.w, nm1, acc1.w);
    }
    if (i < end) {
        int r0 = g_src[i];
        float nm0 = dn * g_dinv[r0];
        float4 v00 = H4[(long)r0 * 64 + lane];
        float4 v01 = H4[(long)r0 * 64 + 32 + lane];
        acc0.x = fmaf(v00.x, nm0, acc0.x); acc0.y = fmaf(v00.y, nm0, acc0.y);
        acc0.z = fmaf(v00.z, nm0, acc0.z); acc0.w = fmaf(v00.w, nm0, acc0.w);
        acc1.x = fmaf(v01.x, nm0, acc1.x); acc1.y = fmaf(v01.y, nm0, acc1.y);
        acc1.z = fmaf(v01.z, nm0, acc1.z); acc1.w = fmaf(v01.w, nm0, acc1.w);
    }

    float4* O4 = (float4*)g_AGG;
    O4[(long)n * 64 + lane] = acc0;
    O4[(long)n * 64 + 32 + lane] = acc1;
}

// ---------------------------------------------------------------------------
// Tiled fp32 GEMM: Out[m,n] = act( A'[m,:] . W[n,:] + bpost[n] )
//   A'[m,k] = PRE ? relu(A[m,k] + bpre[k]) : A[m,k]
// Block tile 128x128, K-tile 16, 256 threads, 8x8 microtile. FFMA-bound.
// ---------------------------------------------------------------------------
template <bool PRE, bool POST>
__global__ void __launch_bounds__(256, 2)
gemm128(const float* __restrict__ A, const float* __restrict__ W,
        const float* __restrict__ bpre, const float* __restrict__ bpost,
        float* __restrict__ Out, int M) {
    __shared__ float As[16][132];
    __shared__ float Ws[16][132];

    const int tid = threadIdx.x;
    const int m0 = blockIdx.x * 128;
    const int n0 = blockIdx.y * 128;
    const int ty = tid >> 4;   // 0..15 (m groups of 8)
    const int tx = tid & 15;   // 0..15 (n groups of 8)

    float acc[8][8] = {};

    for (int k0 = 0; k0 < 256; k0 += 16) {
#pragma unroll
        for (int i = 0; i < 2; i++) {
            int s  = tid + i * 256;   // 0..511
            int r  = s >> 2;          // 0..127
            int c4 = s & 3;           // 0..3
            // A tile (transposed store)
            float4 av = make_float4(0.f, 0.f, 0.f, 0.f);
            int gm = m0 + r;
            if (gm < M)
                av = *(const float4*)(A + (long)gm * 256 + k0 + c4 * 4);
            if (PRE) {
                const float4 bb = *(const float4*)(bpre + k0 + c4 * 4);
                av.x = fmaxf(av.x + bb.x, 0.f);
                av.y = fmaxf(av.y + bb.y, 0.f);
                av.z = fmaxf(av.z + bb.z, 0.f);
                av.w = fmaxf(av.w + bb.w, 0.f);
            }
            As[c4 * 4 + 0][r] = av.x;
            As[c4 * 4 + 1][r] = av.y;
            As[c4 * 4 + 2][r] = av.z;
            As[c4 * 4 + 3][r] = av.w;
            // W tile (transposed store)
            float4 wv = *(const float4*)(W + (long)(n0 + r) * 256 + k0 + c4 * 4);
            Ws[c4 * 4 + 0][r] = wv.x;
            Ws[c4 * 4 + 1][r] = wv.y;
            Ws[c4 * 4 + 2][r] = wv.z;
            Ws[c4 * 4 + 3][r] = wv.w;
        }
        __syncthreads();

#pragma unroll
        for (int k = 0; k < 16; k++) {
            float a[8], b[8];
            *(float4*)(a)     = *(const float4*)&As[k][ty * 8];
            *(float4*)(a + 4) = *(const float4*)&As[k][ty * 8 + 4];
            *(float4*)(b)     = *(const float4*)&Ws[k][tx * 8];
            *(float4*)(b + 4) = *(const float4*)&Ws[k][tx * 8 + 4];
#pragma unroll
            for (int i = 0; i < 8; i++)
#pragma unroll
                for (int j = 0; j < 8; j++)
                    acc[i][j] = fmaf(a[i], b[j], acc[i][j]);
        }
        __syncthreads();
    }

    float4 bb0, bb1;
    if (POST) {
        bb0 = *(const float4*)(bpost + n0 + tx * 8);
        bb1 = *(const float4*)(bpost + n0 + tx * 8 + 4);
    }
#pragma unroll
    for (int i = 0; i < 8; i++) {
        int gm = m0 + ty * 8 + i;
        if (gm >= M) continue;
        float4 v0, v1;
        v0.x = acc[i][0]; v0.y = acc[i][1]; v0.z = acc[i][2]; v0.w = acc[i][3];
        v1.x = acc[i][4]; v1.y = acc[i][5]; v1.z = acc[i][6]; v1.w = acc[i][7];
        if (POST) {
            v0.x = fmaxf(v0.x + bb0.x, 0.f);
            v0.y = fmaxf(v0.y + bb0.y, 0.f);
            v0.z = fmaxf(v0.z + bb0.z, 0.f);
            v0.w = fmaxf(v0.w + bb0.w, 0.f);
            v1.x = fmaxf(v1.x + bb1.x, 0.f);
            v1.y = fmaxf(v1.y + bb1.y, 0.f);
            v1.z = fmaxf(v1.z + bb1.z, 0.f);
            v1.w = fmaxf(v1.w + bb1.w, 0.f);
        }
        *(float4*)(Out + (long)gm * 256 + n0 + tx * 8) = v0;
        *(float4*)(Out + (long)gm * 256 + n0 + tx * 8 + 4) = v1;
    }
}

// ---------------------------------------------------------------------------
// Final layer: out[n] = sigmoid(relu(dot(H2[n,:], W2) + b2)). One warp/node.
// ---------------------------------------------------------------------------
__global__ void final_kernel(const float* __restrict__ W2, const float* __restrict__ b2,
                             float* __restrict__ out, int M) {
    long gt   = (long)blockIdx.x * blockDim.x + threadIdx.x;
    long w    = gt >> 5;
    int  lane = (int)(gt & 31);
    if (w >= M) return;
    const float4* h  = (const float4*)(g_H + w * 256);
    const float4* wv = (const float4*)W2;
    float s = 0.f;
#pragma unroll
    for (int i = 0; i < 2; i++) {
        float4 a = h[lane + i * 32];
        float4 b = wv[lane + i * 32];
        s = fmaf(a.x, b.x, s);
        s = fmaf(a.y, b.y, s);
        s = fmaf(a.z, b.z, s);
        s = fmaf(a.w, b.w, s);
    }
#pragma unroll
    for (int off = 16; off; off >>= 1)
        s += __shfl_xor_sync(0xFFFFFFFFu, s, off);
    if (lane == 0) {
        float v = fmaxf(s + b2[0], 0.f);
        out[w] = 1.f / (1.f + __expf(-v));
    }
}

// ---------------------------------------------------------------------------
extern "C" void kernel_launch(void* const* d_in, const int* in_sizes, int n_in,
                              void* d_out, int out_size) {
    const float* x     = (const float*)d_in[0];
    const void*  ei    = d_in[1];
    const float* W_gcn = (const float*)d_in[2];
    const float* b_gcn = (const float*)d_in[3];
    const float* W1    = (const float*)d_in[4];
    const float* b1    = (const float*)d_in[5];
    const float* W2    = (const float*)d_in[6];
    const float* b2    = (const float*)d_in[7];
    float* out = (float*)d_out;

    const int  M = in_sizes[0] / C;           // 100000
    const long E = (long)in_sizes[1] / 2;     // 3200000

    float *H, *AGG;
    cudaGetSymbolAddress((void**)&H, g_H);
    cudaGetSymbolAddress((void**)&AGG, g_AGG);

    // 1. detect int32 vs int64 edge indices
    detect_kernel<<<1, 256>>>(ei, E);

    // 2. degrees (targets = edge_index[1]) + self loops -> dinv
    zero_deg<<<(M + 255) / 256, 256>>>(M);
    count_deg<<<(int)((E + 255) / 256), 256>>>(ei, E);
    dinv_kernel<<<(M + 255) / 256, 256>>>(M);

    // 3. CSR build: scan degrees -> offsets, bucket edges
    int nb = (M + 1023) / 1024;
    scan_phase1<<<nb, 1024>>>(M);
    scan_phase2<<<1, 128>>>(nb, M, (int)E);
    scan_phase3<<<nb, 1024>>>(M);
    fill_csr<<<(int)((E + 255) / 256), 256>>>(ei, E);

    // 4. H = x @ W_gcn^T
    dim3 ggrid((M + 127) / 128, C / 128);
    gemm128<false, false><<<ggrid, 256>>>(x, W_gcn, nullptr, nullptr, H, M);

    // 5. AGG[n] = dinv[n]^2 * H[n] + sum_{(r,n) in E} dinv[r]dinv[n] H[r]
    {
        long t = (long)M * 32;
        agg_kernel<<<(int)((t + 255) / 256), 256>>>(M);
    }

    // 6. H = relu( relu(AGG + b_gcn) @ W1^T + b1 )
    gemm128<true, true><<<ggrid, 256>>>(AGG, W1, b_gcn, b1, H, M);

    // 7. out = sigmoid(relu(H @ W2^T + b2))
    {
        long t = (long)M * 32;
        final_kernel<<<(int)((t + 255) / 256), 256>>>(W2, b2, out, M);
    }
}

// round 4
// speedup vs baseline: 2.7822x; 1.6078x over previous
#include <cuda_runtime.h>
#include <cuda_bf16.h>
#include <cstdint>

#define NMAX 100000
#define EMAX 3200000
#define C 256

__device__ float g_H[(size_t)NMAX * C];
__device__ float g_AGG[(size_t)NMAX * C];
__device__ int   g_deg[NMAX];
__device__ float g_dinv[NMAX];
__device__ int   g_off[NMAX + 1];
__device__ int   g_cursor[NMAX];
__device__ int   g_src[EMAX];
__device__ int   g_bsum[128];
__device__ int   g_bpre[128];
__device__ int   g_idx64;

// bf16 hi/lo transposed+swizzled weight images: [n-tile(2)][256 k][128 n] bf16
// stored as u32 (bf16x2 along n). 16384 u32 per tile image.
__device__ uint32_t g_W0h[2 * 16384];
__device__ uint32_t g_W0l[2 * 16384];
__device__ uint32_t g_W1h[2 * 16384];
__device__ uint32_t g_W1l[2 * 16384];

// ---------------------------------------------------------------------------
// helpers
// ---------------------------------------------------------------------------
__device__ __forceinline__ uint32_t smem_u32(const void* p) {
    uint32_t a;
    asm("{ .reg .u64 t; cvta.to.shared.u64 t, %1; cvt.u32.u64 %0, t; }" : "=r"(a) : "l"(p));
    return a;
}

__device__ __forceinline__ void ldsm_x4(uint32_t* r, uint32_t addr) {
    asm volatile("ldmatrix.sync.aligned.m8n8.x4.shared.b16 {%0,%1,%2,%3}, [%4];"
                 : "=r"(r[0]), "=r"(r[1]), "=r"(r[2]), "=r"(r[3]) : "r"(addr));
}
__device__ __forceinline__ void ldsm_x4_t(uint32_t* r, uint32_t addr) {
    asm volatile("ldmatrix.sync.aligned.m8n8.x4.trans.shared.b16 {%0,%1,%2,%3}, [%4];"
                 : "=r"(r[0]), "=r"(r[1]), "=r"(r[2]), "=r"(r[3]) : "r"(addr));
}
__device__ __forceinline__ void mma_bf16(float* d, const uint32_t* a, const uint32_t* b) {
    asm volatile(
        "mma.sync.aligned.m16n8k16.row.col.f32.bf16.bf16.f32 "
        "{%0,%1,%2,%3}, {%4,%5,%6,%7}, {%8,%9}, {%0,%1,%2,%3};"
        : "+f"(d[0]), "+f"(d[1]), "+f"(d[2]), "+f"(d[3])
        : "r"(a[0]), "r"(a[1]), "r"(a[2]), "r"(a[3]), "r"(b[0]), "r"(b[1]));
}

// split two fp32 into packed bf16x2 hi and residual lo. element0(lower16)=a.
__device__ __forceinline__ void split_pair(float a, float b, uint32_t& hi, uint32_t& lo) {
    asm("cvt.rn.bf16x2.f32 %0, %1, %2;" : "=r"(hi) : "f"(b), "f"(a));
    float ha = __uint_as_float(hi << 16);
    float hb = __uint_as_float(hi & 0xFFFF0000u);
    float la = a - ha;
    float lb = b - hb;
    asm("cvt.rn.bf16x2.f32 %0, %1, %2;" : "=r"(lo) : "f"(lb), "f"(la));
}

// ---------------------------------------------------------------------------
// edge-index dtype detection
// ---------------------------------------------------------------------------
__global__ void detect_kernel(const void* ei, long n_slots) {
    const int* w = (const int*)ei;
    int tid = threadIdx.x;
    int any = 0;
    long n = n_slots < 2048 ? n_slots : 2048;
    for (long i = tid; i < n; i += blockDim.x)
        if (w[2 * i + 1] != 0) any = 1;
    any = __syncthreads_or(any);
    if (tid == 0) g_idx64 = any ? 0 : 1;
}
__device__ __forceinline__ long fetch_idx(const void* ei, long pos) {
    if (g_idx64) return (long)((const long long*)ei)[pos];
    return (long)((const int*)ei)[pos];
}

// ---------------------------------------------------------------------------
// degree / dinv / CSR build
// ---------------------------------------------------------------------------
__global__ void zero_deg(int M) {
    int i = blockIdx.x * blockDim.x + threadIdx.x;
    if (i < M) g_deg[i] = 0;
}
__global__ void count_deg(const void* ei, long E) {
    long e = (long)blockIdx.x * blockDim.x + threadIdx.x;
    if (e < E) atomicAdd(&g_deg[fetch_idx(ei, E + e)], 1);
}
__global__ void dinv_kernel(int M) {
    int i = blockIdx.x * blockDim.x + threadIdx.x;
    if (i < M) g_dinv[i] = rsqrtf((float)(g_deg[i] + 1));
}
__global__ void scan_phase1(int M) {
    __shared__ int s[1024];
    int tid = threadIdx.x;
    int i = blockIdx.x * 1024 + tid;
    s[tid] = (i < M) ? g_deg[i] : 0;
    __syncthreads();
    for (int d = 512; d > 0; d >>= 1) {
        if (tid < d) s[tid] += s[tid + d];
        __syncthreads();
    }
    if (tid == 0) g_bsum[blockIdx.x] = s[0];
}
__global__ void scan_phase2(int nb, int M, int Etot) {
    __shared__ int s[128];
    int tid = threadIdx.x;
    int v = (tid < nb) ? g_bsum[tid] : 0;
    s[tid] = v;
    __syncthreads();
    for (int d = 1; d < 128; d <<= 1) {
        int t = (tid >= d) ? s[tid - d] : 0;
        __syncthreads();
        s[tid] += t;
        __syncthreads();
    }
    if (tid < nb) g_bpre[tid] = s[tid] - v;
    if (tid == 0) g_off[M] = Etot;
}
__global__ void scan_phase3(int M) {
    __shared__ int s[1024];
    int tid = threadIdx.x;
    int i = blockIdx.x * 1024 + tid;
    int v = (i < M) ? g_deg[i] : 0;
    s[tid] = v;
    __syncthreads();
    for (int d = 1; d < 1024; d <<= 1) {
        int t = (tid >= d) ? s[tid - d] : 0;
        __syncthreads();
        s[tid] += t;
        __syncthreads();
    }
    if (i < M) {
        int excl = s[tid] - v + g_bpre[blockIdx.x];
        g_off[i] = excl;
        g_cursor[i] = excl;
    }
}
__global__ void fill_csr(const void* ei, long E) {
    long e = (long)blockIdx.x * blockDim.x + threadIdx.x;
    if (e < E) {
        int row = (int)fetch_idx(ei, e);
        int col = (int)fetch_idx(ei, E + e);
        g_src[atomicAdd(&g_cursor[col], 1)] = row;
    }
}

// ---------------------------------------------------------------------------
// CSR aggregation, one warp per node
// ---------------------------------------------------------------------------
__global__ void agg_kernel(int M) {
    long gt = (long)blockIdx.x * blockDim.x + threadIdx.x;
    int n = (int)(gt >> 5);
    int lane = (int)(gt & 31);
    if (n >= M) return;

    const float4* H4 = (const float4*)g_H;
    float dn = g_dinv[n];
    float sl = dn * dn;

    float4 a0 = H4[(long)n * 64 + lane];
    float4 a1 = H4[(long)n * 64 + 32 + lane];
    float4 acc0 = make_float4(a0.x * sl, a0.y * sl, a0.z * sl, a0.w * sl);
    float4 acc1 = make_float4(a1.x * sl, a1.y * sl, a1.z * sl, a1.w * sl);

    int i = g_off[n];
    int end = g_off[n + 1];
    for (; i + 1 < end; i += 2) {
        int r0 = g_src[i];
        int r1 = g_src[i + 1];
        float nm0 = dn * g_dinv[r0];
        float nm1 = dn * g_dinv[r1];
        float4 v00 = H4[(long)r0 * 64 + lane];
        float4 v01 = H4[(long)r0 * 64 + 32 + lane];
        float4 v10 = H4[(long)r1 * 64 + lane];
        float4 v11 = H4[(long)r1 * 64 + 32 + lane];
        acc0.x = fmaf(v00.x, nm0, acc0.x); acc0.y = fmaf(v00.y, nm0, acc0.y);
        acc0.z = fmaf(v00.z, nm0, acc0.z); acc0.w = fmaf(v00.w, nm0, acc0.w);
        acc1.x = fmaf(v01.x, nm0, acc1.x); acc1.y = fmaf(v01.y, nm0, acc1.y);
        acc1.z = fmaf(v01.z, nm0, acc1.z); acc1.w = fmaf(v01.w, nm0, acc1.w);
        acc0.x = fmaf(v10.x, nm1, acc0.x); acc0.y = fmaf(v10.y, nm1, acc0.y);
        acc0.z = fmaf(v10.z, nm1, acc0.z); acc0.w = fmaf(v10.w, nm1, acc0.w);
        acc1.x = fmaf(v11.x, nm1, acc1.x); acc1.y = fmaf(v11.y, nm1, acc1.y);
        acc1.z = fmaf(v11.z, nm1, acc1.z); acc1.w = fmaf(v11.w, nm1, acc1.w);
    }
    if (i < end) {
        int r0 = g_src[i];
        float nm0 = dn * g_dinv[r0];
        float4 v00 = H4[(long)r0 * 64 + lane];
        float4 v01 = H4[(long)r0 * 64 + 32 + lane];
        acc0.x = fmaf(v00.x, nm0, acc0.x); acc0.y = fmaf(v00.y, nm0, acc0.y);
        acc0.z = fmaf(v00.z, nm0, acc0.z); acc0.w = fmaf(v00.w, nm0, acc0.w);
        acc1.x = fmaf(v01.x, nm0, acc1.x); acc1.y = fmaf(v01.y, nm0, acc1.y);
        acc1.z = fmaf(v01.z, nm0, acc1.z); acc1.w = fmaf(v01.w, nm0, acc1.w);
    }

    float4* O4 = (float4*)g_AGG;
    O4[(long)n * 64 + lane] = acc0;
    O4[(long)n * 64 + 32 + lane] = acc1;
}

// ---------------------------------------------------------------------------
// Weight prep: W[256,256] fp32 -> per n-tile transposed image Bt[k][n] bf16
// hi/lo, with xor-swizzle for conflict-free ldmatrix.trans.
// u32 at byte offset: k*256 + (((n>>3)^(k&7))<<4) + (n&7)*2  (n even)
// ---------------------------------------------------------------------------
__global__ void prep_weights(const float* __restrict__ W,
                             uint32_t* __restrict__ img_h, uint32_t* __restrict__ img_l) {
    int idx = blockIdx.x * blockDim.x + threadIdx.x;  // 2*256*64 = 32768
    if (idx >= 32768) return;
    int tile = idx >> 14;
    int k = (idx >> 6) & 255;
    int np = idx & 63;
    int n = np * 2;
    int gn = tile * 128 + n;
    float a = W[gn * 256 + k];
    float b = W[(gn + 1) * 256 + k];
    uint32_t hi, lo;
    split_pair(a, b, hi, lo);
    uint32_t boff = (uint32_t)k * 256 + ((((n >> 3) ^ (k & 7)) << 4) | ((n & 7) * 2));
    img_h[tile * 16384 + (boff >> 2)] = hi;
    img_l[tile * 16384 + (boff >> 2)] = lo;
}

// ---------------------------------------------------------------------------
// HMMA GEMM, 3x bf16 split, persistent blocks.
// Out[m,n] = act( A'[m,:] . W[n,:] + bpost[n] ),  A' = PRE ? relu(A+bpre) : A
// grid (74, 2). Block: 256 thr (8 warps, 4m x 2n). Tile M=128, N=128, full K.
// smem: Bhi 64KB | Blo 64KB | Ahi 16KB | Alo 16KB  (A chunked K=64)
// ---------------------------------------------------------------------------
#define SM_BHI 0
#define SM_BLO 65536
#define SM_AHI 131072
#define SM_ALO 147456
#define SM_TOT 163840

template <bool PRE, bool POST>
__global__ void __launch_bounds__(256, 1)
gemm_hmma(const float* __restrict__ A,
          const uint32_t* __restrict__ img_h, const uint32_t* __restrict__ img_l,
          const float* __restrict__ bpre, const float* __restrict__ bpost,
          float* __restrict__ Out, int M, int ntiles) {
    extern __shared__ char smem[];
    const uint32_t sb = smem_u32(smem);
    const int tid = threadIdx.x;
    const int lane = tid & 31;
    const int wid = tid >> 5;
    const int wm = wid & 3;
    const int wn = wid >> 2;
    const int n0 = blockIdx.y * 128;

    // ---- copy B images (once per block; swizzle baked into image) ----
    {
        const uint4* sh = (const uint4*)(img_h + blockIdx.y * 16384);
        const uint4* sl = (const uint4*)(img_l + blockIdx.y * 16384);
        uint4* dh = (uint4*)(smem + SM_BHI);
        uint4* dl = (uint4*)(smem + SM_BLO);
#pragma unroll
        for (int i = 0; i < 16; i++) {
            dh[tid + i * 256] = sh[tid + i * 256];
            dl[tid + i * 256] = sl[tid + i * 256];
        }
    }

    // fill-thread coords: thread handles row frow, k-half fkh of each chunk
    const int frow = tid >> 1;
    const int fkh = (tid & 1) * 32;

    // prefetch chunk 0 of first tile
    float4 pf[8];
    int t = blockIdx.x;
    {
        bool ok = (t < ntiles) && (t * 128 + frow < M);
        const float* Ab = A + (long)(t * 128 + frow) * 256 + fkh;
#pragma unroll
        for (int j = 0; j < 8; j++)
            pf[j] = ok ? *(const float4*)(Ab + j * 4) : make_float4(0.f, 0.f, 0.f, 0.f);
    }

    const int g = lane >> 3;

    for (; t < ntiles; t += 74) {
        const int m0 = t * 128;
        float acc[2][8][4];
#pragma unroll
        for (int a_ = 0; a_ < 2; a_++)
#pragma unroll
            for (int b_ = 0; b_ < 8; b_++)
#pragma unroll
                for (int c_ = 0; c_ < 4; c_++) acc[a_][b_][c_] = 0.f;

        for (int ch = 0; ch < 4; ch++) {
            // ---- convert prefetched chunk -> A smem (hi/lo bf16, swizzled) ----
            {
                uint32_t base_h = sb + SM_AHI + frow * 128;
                uint32_t base_l = sb + SM_ALO + frow * 128;
#pragma unroll
                for (int j = 0; j < 8; j++) {
                    float4 v = pf[j];
                    if (PRE) {
                        const float4 bb = *(const float4*)(bpre + ch * 64 + fkh + j * 4);
                        v.x = fmaxf(v.x + bb.x, 0.f);
                        v.y = fmaxf(v.y + bb.y, 0.f);
                        v.z = fmaxf(v.z + bb.z, 0.f);
                        v.w = fmaxf(v.w + bb.w, 0.f);
                    }
                    uint32_t h0, l0, h1, l1;
                    split_pair(v.x, v.y, h0, l0);
                    split_pair(v.z, v.w, h1, l1);
                    int kk = fkh + j * 4;
                    uint32_t off = ((((kk >> 3) ^ (frow & 7)) << 4) | ((kk & 7) * 2));
                    asm volatile("st.shared.v2.b32 [%0], {%1, %2};"
                                 :: "r"(base_h + off), "r"(h0), "r"(h1) : "memory");
                    asm volatile("st.shared.v2.b32 [%0], {%1, %2};"
                                 :: "r"(base_l + off), "r"(l0), "r"(l1) : "memory");
                }
            }
            __syncthreads();

            // ---- prefetch next chunk (hidden under MMA) ----
            {
                int nc = ch + 1;
                int nt = t;
                if (nc == 4) { nc = 0; nt = t + 74; }
                if (nt < ntiles) {
                    bool ok = (nt * 128 + frow) < M;
                    const float* Ab = A + (long)(nt * 128 + frow) * 256 + nc * 64 + fkh;
#pragma unroll
                    for (int j = 0; j < 8; j++)
                        pf[j] = ok ? *(const float4*)(Ab + j * 4) : make_float4(0.f, 0.f, 0.f, 0.f);
                }
            }

            // ---- MMA over 4 k16 steps of this chunk ----
#pragma unroll
            for (int ks = 0; ks < 4; ks++) {
                const int klocal = ks * 16;
                const int kglob = ch * 64 + klocal;

                uint32_t ah[2][4], al[2][4];
#pragma unroll
                for (int mf = 0; mf < 2; mf++) {
                    int m = wm * 32 + mf * 16 + ((g & 1) << 3) + (lane & 7);
                    int kc = klocal + ((g >> 1) << 3);
                    uint32_t off = (uint32_t)m * 128 + ((((kc >> 3) ^ (m & 7)) << 4));
                    ldsm_x4(ah[mf], sb + SM_AHI + off);
                    ldsm_x4(al[mf], sb + SM_ALO + off);
                }

                uint32_t bh[8][2], bl[8][2];
#pragma unroll
                for (int q = 0; q < 4; q++) {
                    int nb = wn * 64 + q * 16 + ((g >> 1) << 3);
                    int kr = kglob + ((g & 1) << 3) + (lane & 7);
                    uint32_t off = (uint32_t)kr * 256 + ((((nb >> 3) ^ (kr & 7)) << 4));
                    uint32_t r[4], s[4];
                    ldsm_x4_t(r, sb + SM_BHI + off);
                    ldsm_x4_t(s, sb + SM_BLO + off);
                    bh[q * 2][0] = r[0]; bh[q * 2][1] = r[1];
                    bh[q * 2 + 1][0] = r[2]; bh[q * 2 + 1][1] = r[3];
                    bl[q * 2][0] = s[0]; bl[q * 2][1] = s[1];
                    bl[q * 2 + 1][0] = s[2]; bl[q * 2 + 1][1] = s[3];
                }

#pragma unroll
                for (int mf = 0; mf < 2; mf++)
#pragma unroll
                    for (int nf = 0; nf < 8; nf++) {
                        mma_bf16(acc[mf][nf], ah[mf], bh[nf]);
                        mma_bf16(acc[mf][nf], ah[mf], bl[nf]);
                        mma_bf16(acc[mf][nf], al[mf], bh[nf]);
                    }
            }
            __syncthreads();
        }

        // ---- epilogue ----
#pragma unroll
        for (int mf = 0; mf < 2; mf++) {
#pragma unroll
            for (int half = 0; half < 2; half++) {
                int m = m0 + wm * 32 + mf * 16 + (lane >> 2) + half * 8;
                if (m < M) {
                    float* op = Out + (long)m * 256 + n0 + wn * 64 + 2 * (lane & 3);
#pragma unroll
                    for (int nf = 0; nf < 8; nf++) {
                        float2 v;
                        v.x = acc[mf][nf][half * 2];
                        v.y = acc[mf][nf][half * 2 + 1];
                        if (POST) {
                            const float2 bb = *(const float2*)(bpost + n0 + wn * 64 + nf * 8 + 2 * (lane & 3));
                            v.x = fmaxf(v.x + bb.x, 0.f);
                            v.y = fmaxf(v.y + bb.y, 0.f);
                        }
                        *(float2*)(op + nf * 8) = v;
                    }
                }
            }
        }
    }
}

// ---------------------------------------------------------------------------
// Final layer
// ---------------------------------------------------------------------------
__global__ void final_kernel(const float* __restrict__ W2, const float* __restrict__ b2,
                             float* __restrict__ out, int M) {
    long gt = (long)blockIdx.x * blockDim.x + threadIdx.x;
    long w = gt >> 5;
    int lane = (int)(gt & 31);
    if (w >= M) return;
    const float4* h = (const float4*)(g_H + w * 256);
    const float4* wv = (const float4*)W2;
    float s = 0.f;
#pragma unroll
    for (int i = 0; i < 2; i++) {
        float4 a = h[lane + i * 32];
        float4 b = wv[lane + i * 32];
        s = fmaf(a.x, b.x, s);
        s = fmaf(a.y, b.y, s);
        s = fmaf(a.z, b.z, s);
        s = fmaf(a.w, b.w, s);
    }
#pragma unroll
    for (int off = 16; off; off >>= 1)
        s += __shfl_xor_sync(0xFFFFFFFFu, s, off);
    if (lane == 0) {
        float v = fmaxf(s + b2[0], 0.f);
        out[w] = 1.f / (1.f + __expf(-v));
    }
}

// ---------------------------------------------------------------------------
extern "C" void kernel_launch(void* const* d_in, const int* in_sizes, int n_in,
                              void* d_out, int out_size) {
    const float* x     = (const float*)d_in[0];
    const void*  ei    = d_in[1];
    const float* W_gcn = (const float*)d_in[2];
    const float* b_gcn = (const float*)d_in[3];
    const float* W1    = (const float*)d_in[4];
    const float* b1    = (const float*)d_in[5];
    const float* W2    = (const float*)d_in[6];
    const float* b2    = (const float*)d_in[7];
    float* out = (float*)d_out;

    const int  M = in_sizes[0] / C;        // 100000
    const long E = (long)in_sizes[1] / 2;  // 3200000
    const int ntiles = (M + 127) / 128;

    float *H, *AGG;
    cudaGetSymbolAddress((void**)&H, g_H);
    cudaGetSymbolAddress((void**)&AGG, g_AGG);
    uint32_t *W0h, *W0l, *W1h, *W1l;
    cudaGetSymbolAddress((void**)&W0h, g_W0h);
    cudaGetSymbolAddress((void**)&W0l, g_W0l);
    cudaGetSymbolAddress((void**)&W1h, g_W1h);
    cudaGetSymbolAddress((void**)&W1l, g_W1l);

    static bool attr_done = false;
    if (!attr_done) {
        cudaFuncSetAttribute(gemm_hmma<false, false>,
                             cudaFuncAttributeMaxDynamicSharedMemorySize, SM_TOT);
        cudaFuncSetAttribute(gemm_hmma<true, true>,
                             cudaFuncAttributeMaxDynamicSharedMemorySize, SM_TOT);
        attr_done = true;
    }

    // 1. dtype detect + degrees + dinv
    detect_kernel<<<1, 256>>>(ei, E);
    zero_deg<<<(M + 255) / 256, 256>>>(M);
    count_deg<<<(int)((E + 255) / 256), 256>>>(ei, E);
    dinv_kernel<<<(M + 255) / 256, 256>>>(M);

    // 2. weight images (bf16 hi/lo, transposed + swizzled)
    prep_weights<<<128, 256>>>(W_gcn, W0h, W0l);
    prep_weights<<<128, 256>>>(W1, W1h, W1l);

    // 3. CSR build
    int nb = (M + 1023) / 1024;
    scan_phase1<<<nb, 1024>>>(M);
    scan_phase2<<<1, 128>>>(nb, M, (int)E);
    scan_phase3<<<nb, 1024>>>(M);
    fill_csr<<<(int)((E + 255) / 256), 256>>>(ei, E);

    // 4. H = x @ W_gcn^T  (HMMA, 3x bf16 split)
    dim3 ggrid(74, 2);
    gemm_hmma<false, false><<<ggrid, 256, SM_TOT>>>(x, W0h, W0l, nullptr, nullptr, H, M, ntiles);

    // 5. AGG aggregation
    {
        long tcount = (long)M * 32;
        agg_kernel<<<(int)((tcount + 255) / 256), 256>>>(M);
    }

    // 6. H = relu( relu(AGG + b_gcn) @ W1^T + b1 )
    gemm_hmma<true, true><<<ggrid, 256, SM_TOT>>>(AGG, W1h, W1l, b_gcn, b1, H, M, ntiles);

    // 7. out
    {
        long tcount = (long)M * 32;
        final_kernel<<<(int)((tcount + 255) / 256), 256>>>(W2, b2, out, M);
    }
}

// round 5
// speedup vs baseline: 3.3878x; 1.2176x over previous
#include <cuda_runtime.h>
#include <cuda_bf16.h>
#include <cuda_fp16.h>
#include <cstdint>

#define NMAX 100000
#define EMAX 3200000
#define C 256

__device__ __half g_H16[(size_t)NMAX * C];  // GEMM1 output (fp16, agg source)
__device__ float g_H[(size_t)NMAX * C];     // GEMM2 output (fp32, final input)
__device__ float g_AGG[(size_t)NMAX * C];
__device__ int   g_deg[NMAX];
__device__ float g_dinv[NMAX];
__device__ int   g_off[NMAX + 1];
__device__ int   g_cursor[NMAX];
__device__ int   g_src[EMAX];
__device__ int   g_bsum[128];
__device__ int   g_bpre[128];
__device__ int   g_idx64;

// bf16 hi/lo transposed+swizzled weight images
__device__ uint32_t g_W0h[2 * 16384];
__device__ uint32_t g_W0l[2 * 16384];
__device__ uint32_t g_W1h[2 * 16384];
__device__ uint32_t g_W1l[2 * 16384];

// ---------------------------------------------------------------------------
// helpers
// ---------------------------------------------------------------------------
__device__ __forceinline__ uint32_t smem_u32(const void* p) {
    uint32_t a;
    asm("{ .reg .u64 t; cvta.to.shared.u64 t, %1; cvt.u32.u64 %0, t; }" : "=r"(a) : "l"(p));
    return a;
}
__device__ __forceinline__ void ldsm_x4(uint32_t* r, uint32_t addr) {
    asm volatile("ldmatrix.sync.aligned.m8n8.x4.shared.b16 {%0,%1,%2,%3}, [%4];"
                 : "=r"(r[0]), "=r"(r[1]), "=r"(r[2]), "=r"(r[3]) : "r"(addr));
}
__device__ __forceinline__ void ldsm_x4_t(uint32_t* r, uint32_t addr) {
    asm volatile("ldmatrix.sync.aligned.m8n8.x4.trans.shared.b16 {%0,%1,%2,%3}, [%4];"
                 : "=r"(r[0]), "=r"(r[1]), "=r"(r[2]), "=r"(r[3]) : "r"(addr));
}
__device__ __forceinline__ void mma_bf16(float* d, const uint32_t* a, const uint32_t* b) {
    asm volatile(
        "mma.sync.aligned.m16n8k16.row.col.f32.bf16.bf16.f32 "
        "{%0,%1,%2,%3}, {%4,%5,%6,%7}, {%8,%9}, {%0,%1,%2,%3};"
        : "+f"(d[0]), "+f"(d[1]), "+f"(d[2]), "+f"(d[3])
        : "r"(a[0]), "r"(a[1]), "r"(a[2]), "r"(a[3]), "r"(b[0]), "r"(b[1]));
}
__device__ __forceinline__ void split_pair(float a, float b, uint32_t& hi, uint32_t& lo) {
    asm("cvt.rn.bf16x2.f32 %0, %1, %2;" : "=r"(hi) : "f"(b), "f"(a));
    float ha = __uint_as_float(hi << 16);
    float hb = __uint_as_float(hi & 0xFFFF0000u);
    float la = a - ha;
    float lb = b - hb;
    asm("cvt.rn.bf16x2.f32 %0, %1, %2;" : "=r"(lo) : "f"(lb), "f"(la));
}

// ---------------------------------------------------------------------------
// edge-index dtype detection
// ---------------------------------------------------------------------------
__global__ void detect_kernel(const void* ei, long n_slots) {
    const int* w = (const int*)ei;
    int tid = threadIdx.x;
    int any = 0;
    long n = n_slots < 2048 ? n_slots : 2048;
    for (long i = tid; i < n; i += blockDim.x)
        if (w[2 * i + 1] != 0) any = 1;
    any = __syncthreads_or(any);
    if (tid == 0) g_idx64 = any ? 0 : 1;
}
__device__ __forceinline__ long fetch_idx(const void* ei, long pos) {
    if (g_idx64) return (long)((const long long*)ei)[pos];
    return (long)((const int*)ei)[pos];
}

// ---------------------------------------------------------------------------
// degree / dinv / CSR build
// ---------------------------------------------------------------------------
__global__ void zero_deg(int M) {
    int i = blockIdx.x * blockDim.x + threadIdx.x;
    if (i < M) g_deg[i] = 0;
}
__global__ void count_deg(const void* ei, long E) {
    long e = (long)blockIdx.x * blockDim.x + threadIdx.x;
    if (e < E) atomicAdd(&g_deg[fetch_idx(ei, E + e)], 1);
}
__global__ void dinv_kernel(int M) {
    int i = blockIdx.x * blockDim.x + threadIdx.x;
    if (i < M) g_dinv[i] = rsqrtf((float)(g_deg[i] + 1));
}
__global__ void scan_phase1(int M) {
    __shared__ int s[1024];
    int tid = threadIdx.x;
    int i = blockIdx.x * 1024 + tid;
    s[tid] = (i < M) ? g_deg[i] : 0;
    __syncthreads();
    for (int d = 512; d > 0; d >>= 1) {
        if (tid < d) s[tid] += s[tid + d];
        __syncthreads();
    }
    if (tid == 0) g_bsum[blockIdx.x] = s[0];
}
__global__ void scan_phase2(int nb, int M, int Etot) {
    __shared__ int s[128];
    int tid = threadIdx.x;
    int v = (tid < nb) ? g_bsum[tid] : 0;
    s[tid] = v;
    __syncthreads();
    for (int d = 1; d < 128; d <<= 1) {
        int t = (tid >= d) ? s[tid - d] : 0;
        __syncthreads();
        s[tid] += t;
        __syncthreads();
    }
    if (tid < nb) g_bpre[tid] = s[tid] - v;
    if (tid == 0) g_off[M] = Etot;
}
__global__ void scan_phase3(int M) {
    __shared__ int s[1024];
    int tid = threadIdx.x;
    int i = blockIdx.x * 1024 + tid;
    int v = (i < M) ? g_deg[i] : 0;
    s[tid] = v;
    __syncthreads();
    for (int d = 1; d < 1024; d <<= 1) {
        int t = (tid >= d) ? s[tid - d] : 0;
        __syncthreads();
        s[tid] += t;
        __syncthreads();
    }
    if (i < M) {
        int excl = s[tid] - v + g_bpre[blockIdx.x];
        g_off[i] = excl;
        g_cursor[i] = excl;
    }
}
__global__ void fill_csr(const void* ei, long E) {
    long e = (long)blockIdx.x * blockDim.x + threadIdx.x;
    if (e < E) {
        int row = (int)fetch_idx(ei, e);
        int col = (int)fetch_idx(ei, E + e);
        g_src[atomicAdd(&g_cursor[col], 1)] = row;
    }
}

// ---------------------------------------------------------------------------
// CSR aggregation from fp16 H, one warp per node, 4-edge unroll.
// lane handles 8 channels: [lane*8, lane*8+8)
// ---------------------------------------------------------------------------
__device__ __forceinline__ void h8_fma(uint4 v, float nm, float* acc) {
    float2 f;
    f = __half22float2(*(const __half2*)&v.x);
    acc[0] = fmaf(f.x, nm, acc[0]); acc[1] = fmaf(f.y, nm, acc[1]);
    f = __half22float2(*(const __half2*)&v.y);
    acc[2] = fmaf(f.x, nm, acc[2]); acc[3] = fmaf(f.y, nm, acc[3]);
    f = __half22float2(*(const __half2*)&v.z);
    acc[4] = fmaf(f.x, nm, acc[4]); acc[5] = fmaf(f.y, nm, acc[5]);
    f = __half22float2(*(const __half2*)&v.w);
    acc[6] = fmaf(f.x, nm, acc[6]); acc[7] = fmaf(f.y, nm, acc[7]);
}

__global__ void agg_kernel(int M) {
    long gt = (long)blockIdx.x * blockDim.x + threadIdx.x;
    int n = (int)(gt >> 5);
    int lane = (int)(gt & 31);
    if (n >= M) return;

    const uint4* H16 = (const uint4*)g_H16;   // 32 uint4 per row
    float dn = g_dinv[n];
    float acc[8] = {};

    // self loop (fp16 source)
    h8_fma(H16[(long)n * 32 + lane], dn * dn, acc);

    int i = g_off[n];
    int end = g_off[n + 1];
    for (; i + 3 < end; i += 4) {
        int r0 = g_src[i], r1 = g_src[i + 1], r2 = g_src[i + 2], r3 = g_src[i + 3];
        float nm0 = dn * g_dinv[r0];
        float nm1 = dn * g_dinv[r1];
        float nm2 = dn * g_dinv[r2];
        float nm3 = dn * g_dinv[r3];
        uint4 v0 = H16[(long)r0 * 32 + lane];
        uint4 v1 = H16[(long)r1 * 32 + lane];
        uint4 v2 = H16[(long)r2 * 32 + lane];
        uint4 v3 = H16[(long)r3 * 32 + lane];
        h8_fma(v0, nm0, acc);
        h8_fma(v1, nm1, acc);
        h8_fma(v2, nm2, acc);
        h8_fma(v3, nm3, acc);
    }
    for (; i < end; i++) {
        int r0 = g_src[i];
        h8_fma(H16[(long)r0 * 32 + lane], dn * g_dinv[r0], acc);
    }

    float4* O4 = (float4*)(g_AGG + (long)n * 256 + lane * 8);
    O4[0] = make_float4(acc[0], acc[1], acc[2], acc[3]);
    O4[1] = make_float4(acc[4], acc[5], acc[6], acc[7]);
}

// ---------------------------------------------------------------------------
// Weight prep (unchanged from R4)
// ---------------------------------------------------------------------------
__global__ void prep_weights(const float* __restrict__ W,
                             uint32_t* __restrict__ img_h, uint32_t* __restrict__ img_l) {
    int idx = blockIdx.x * blockDim.x + threadIdx.x;
    if (idx >= 32768) return;
    int tile = idx >> 14;
    int k = (idx >> 6) & 255;
    int np = idx & 63;
    int n = np * 2;
    int gn = tile * 128 + n;
    float a = W[gn * 256 + k];
    float b = W[(gn + 1) * 256 + k];
    uint32_t hi, lo;
    split_pair(a, b, hi, lo);
    uint32_t boff = (uint32_t)k * 256 + ((((n >> 3) ^ (k & 7)) << 4) | ((n & 7) * 2));
    img_h[tile * 16384 + (boff >> 2)] = hi;
    img_l[tile * 16384 + (boff >> 2)] = lo;
}

// ---------------------------------------------------------------------------
// HMMA GEMM, 3x bf16 split, persistent blocks. Optional fp16 or fp32 output.
// ---------------------------------------------------------------------------
#define SM_BHI 0
#define SM_BLO 65536
#define SM_AHI 131072
#define SM_ALO 147456
#define SM_TOT 163840

template <bool PRE, bool POST, bool OUT16>
__global__ void __launch_bounds__(256, 1)
gemm_hmma(const float* __restrict__ A,
          const uint32_t* __restrict__ img_h, const uint32_t* __restrict__ img_l,
          const float* __restrict__ bpre, const float* __restrict__ bpost,
          float* __restrict__ Out, __half* __restrict__ Out16, int M, int ntiles) {
    extern __shared__ char smem[];
    const uint32_t sb = smem_u32(smem);
    const int tid = threadIdx.x;
    const int lane = tid & 31;
    const int wid = tid >> 5;
    const int wm = wid & 3;
    const int wn = wid >> 2;
    const int n0 = blockIdx.y * 128;

    // ---- copy B images ----
    {
        const uint4* sh = (const uint4*)(img_h + blockIdx.y * 16384);
        const uint4* sl = (const uint4*)(img_l + blockIdx.y * 16384);
        uint4* dh = (uint4*)(smem + SM_BHI);
        uint4* dl = (uint4*)(smem + SM_BLO);
#pragma unroll
        for (int i = 0; i < 16; i++) {
            dh[tid + i * 256] = sh[tid + i * 256];
            dl[tid + i * 256] = sl[tid + i * 256];
        }
    }

    const int frow = tid >> 1;
    const int fkh = (tid & 1) * 32;

    float4 pf[8];
    int t = blockIdx.x;
    {
        bool ok = (t < ntiles) && (t * 128 + frow < M);
        const float* Ab = A + (long)(t * 128 + frow) * 256 + fkh;
#pragma unroll
        for (int j = 0; j < 8; j++)
            pf[j] = ok ? *(const float4*)(Ab + j * 4) : make_float4(0.f, 0.f, 0.f, 0.f);
    }

    const int g = lane >> 3;

    for (; t < ntiles; t += 74) {
        const int m0 = t * 128;
        float acc[2][8][4];
#pragma unroll
        for (int a_ = 0; a_ < 2; a_++)
#pragma unroll
            for (int b_ = 0; b_ < 8; b_++)
#pragma unroll
                for (int c_ = 0; c_ < 4; c_++) acc[a_][b_][c_] = 0.f;

        for (int ch = 0; ch < 4; ch++) {
            {
                uint32_t base_h = sb + SM_AHI + frow * 128;
                uint32_t base_l = sb + SM_ALO + frow * 128;
#pragma unroll
                for (int j = 0; j < 8; j++) {
                    float4 v = pf[j];
                    if (PRE) {
                        const float4 bb = *(const float4*)(bpre + ch * 64 + fkh + j * 4);
                        v.x = fmaxf(v.x + bb.x, 0.f);
                        v.y = fmaxf(v.y + bb.y, 0.f);
                        v.z = fmaxf(v.z + bb.z, 0.f);
                        v.w = fmaxf(v.w + bb.w, 0.f);
                    }
                    uint32_t h0, l0, h1, l1;
                    split_pair(v.x, v.y, h0, l0);
                    split_pair(v.z, v.w, h1, l1);
                    int kk = fkh + j * 4;
                    uint32_t off = ((((kk >> 3) ^ (frow & 7)) << 4) | ((kk & 7) * 2));
                    asm volatile("st.shared.v2.b32 [%0], {%1, %2};"
                                 :: "r"(base_h + off), "r"(h0), "r"(h1) : "memory");
                    asm volatile("st.shared.v2.b32 [%0], {%1, %2};"
                                 :: "r"(base_l + off), "r"(l0), "r"(l1) : "memory");
                }
            }
            __syncthreads();

            {
                int nc = ch + 1;
                int nt = t;
                if (nc == 4) { nc = 0; nt = t + 74; }
                if (nt < ntiles) {
                    bool ok = (nt * 128 + frow) < M;
                    const float* Ab = A + (long)(nt * 128 + frow) * 256 + nc * 64 + fkh;
#pragma unroll
                    for (int j = 0; j < 8; j++)
                        pf[j] = ok ? *(const float4*)(Ab + j * 4) : make_float4(0.f, 0.f, 0.f, 0.f);
                }
            }

#pragma unroll
            for (int ks = 0; ks < 4; ks++) {
                const int klocal = ks * 16;
                const int kglob = ch * 64 + klocal;

                uint32_t ah[2][4], al[2][4];
#pragma unroll
                for (int mf = 0; mf < 2; mf++) {
                    int m = wm * 32 + mf * 16 + ((g & 1) << 3) + (lane & 7);
                    int kc = klocal + ((g >> 1) << 3);
                    uint32_t off = (uint32_t)m * 128 + ((((kc >> 3) ^ (m & 7)) << 4));
                    ldsm_x4(ah[mf], sb + SM_AHI + off);
                    ldsm_x4(al[mf], sb + SM_ALO + off);
                }

                uint32_t bh[8][2], bl[8][2];
#pragma unroll
                for (int q = 0; q < 4; q++) {
                    int nb = wn * 64 + q * 16 + ((g >> 1) << 3);
                    int kr = kglob + ((g & 1) << 3) + (lane & 7);
                    uint32_t off = (uint32_t)kr * 256 + ((((nb >> 3) ^ (kr & 7)) << 4));
                    uint32_t r[4], s[4];
                    ldsm_x4_t(r, sb + SM_BHI + off);
                    ldsm_x4_t(s, sb + SM_BLO + off);
                    bh[q * 2][0] = r[0]; bh[q * 2][1] = r[1];
                    bh[q * 2 + 1][0] = r[2]; bh[q * 2 + 1][1] = r[3];
                    bl[q * 2][0] = s[0]; bl[q * 2][1] = s[1];
                    bl[q * 2 + 1][0] = s[2]; bl[q * 2 + 1][1] = s[3];
                }

#pragma unroll
                for (int mf = 0; mf < 2; mf++)
#pragma unroll
                    for (int nf = 0; nf < 8; nf++) {
                        mma_bf16(acc[mf][nf], ah[mf], bh[nf]);
                        mma_bf16(acc[mf][nf], ah[mf], bl[nf]);
                        mma_bf16(acc[mf][nf], al[mf], bh[nf]);
                    }
            }
            __syncthreads();
        }

        // ---- epilogue ----
#pragma unroll
        for (int mf = 0; mf < 2; mf++) {
#pragma unroll
            for (int half = 0; half < 2; half++) {
                int m = m0 + wm * 32 + mf * 16 + (lane >> 2) + half * 8;
                if (m < M) {
                    long base = (long)m * 256 + n0 + wn * 64 + 2 * (lane & 3);
#pragma unroll
                    for (int nf = 0; nf < 8; nf++) {
                        float2 v;
                        v.x = acc[mf][nf][half * 2];
                        v.y = acc[mf][nf][half * 2 + 1];
                        if (POST) {
                            const float2 bb = *(const float2*)(bpost + n0 + wn * 64 + nf * 8 + 2 * (lane & 3));
                            v.x = fmaxf(v.x + bb.x, 0.f);
                            v.y = fmaxf(v.y + bb.y, 0.f);
                        }
                        if (OUT16) {
                            __half2 h = __float22half2_rn(v);
                            *(__half2*)(Out16 + base + nf * 8) = h;
                        } else {
                            *(float2*)(Out + base + nf * 8) = v;
                        }
                    }
                }
            }
        }
    }
}

// ---------------------------------------------------------------------------
// Final layer
// ---------------------------------------------------------------------------
__global__ void final_kernel(const float* __restrict__ W2, const float* __restrict__ b2,
                             float* __restrict__ out, int M) {
    long gt = (long)blockIdx.x * blockDim.x + threadIdx.x;
    long w = gt >> 5;
    int lane = (int)(gt & 31);
    if (w >= M) return;
    const float4* h = (const float4*)(g_H + w * 256);
    const float4* wv = (const float4*)W2;
    float s = 0.f;
#pragma unroll
    for (int i = 0; i < 2; i++) {
        float4 a = h[lane + i * 32];
        float4 b = wv[lane + i * 32];
        s = fmaf(a.x, b.x, s);
        s = fmaf(a.y, b.y, s);
        s = fmaf(a.z, b.z, s);
        s = fmaf(a.w, b.w, s);
    }
#pragma unroll
    for (int off = 16; off; off >>= 1)
        s += __shfl_xor_sync(0xFFFFFFFFu, s, off);
    if (lane == 0) {
        float v = fmaxf(s + b2[0], 0.f);
        out[w] = 1.f / (1.f + __expf(-v));
    }
}

// ---------------------------------------------------------------------------
extern "C" void kernel_launch(void* const* d_in, const int* in_sizes, int n_in,
                              void* d_out, int out_size) {
    const float* x     = (const float*)d_in[0];
    const void*  ei    = d_in[1];
    const float* W_gcn = (const float*)d_in[2];
    const float* b_gcn = (const float*)d_in[3];
    const float* W1    = (const float*)d_in[4];
    const float* b1    = (const float*)d_in[5];
    const float* W2    = (const float*)d_in[6];
    const float* b2    = (const float*)d_in[7];
    float* out = (float*)d_out;

    const int  M = in_sizes[0] / C;
    const long E = (long)in_sizes[1] / 2;
    const int ntiles = (M + 127) / 128;

    float *H, *AGG;
    __half* H16;
    cudaGetSymbolAddress((void**)&H, g_H);
    cudaGetSymbolAddress((void**)&AGG, g_AGG);
    cudaGetSymbolAddress((void**)&H16, g_H16);
    uint32_t *W0h, *W0l, *W1h, *W1l;
    cudaGetSymbolAddress((void**)&W0h, g_W0h);
    cudaGetSymbolAddress((void**)&W0l, g_W0l);
    cudaGetSymbolAddress((void**)&W1h, g_W1h);
    cudaGetSymbolAddress((void**)&W1l, g_W1l);

    static bool attr_done = false;
    if (!attr_done) {
        cudaFuncSetAttribute(gemm_hmma<false, false, true>,
                             cudaFuncAttributeMaxDynamicSharedMemorySize, SM_TOT);
        cudaFuncSetAttribute(gemm_hmma<true, true, false>,
                             cudaFuncAttributeMaxDynamicSharedMemorySize, SM_TOT);
        attr_done = true;
    }

    // 1. dtype detect + degrees + dinv
    detect_kernel<<<1, 256>>>(ei, E);
    zero_deg<<<(M + 255) / 256, 256>>>(M);
    count_deg<<<(int)((E + 255) / 256), 256>>>(ei, E);
    dinv_kernel<<<(M + 255) / 256, 256>>>(M);

    // 2. weight images
    prep_weights<<<128, 256>>>(W_gcn, W0h, W0l);
    prep_weights<<<128, 256>>>(W1, W1h, W1l);

    // 3. CSR build
    int nb = (M + 1023) / 1024;
    scan_phase1<<<nb, 1024>>>(M);
    scan_phase2<<<1, 128>>>(nb, M, (int)E);
    scan_phase3<<<nb, 1024>>>(M);
    fill_csr<<<(int)((E + 255) / 256), 256>>>(ei, E);

    // 4. H16 = fp16( x @ W_gcn^T )
    dim3 ggrid(74, 2);
    gemm_hmma<false, false, true><<<ggrid, 256, SM_TOT>>>(
        x, W0h, W0l, nullptr, nullptr, nullptr, H16, M, ntiles);

    // 5. AGG aggregation (fp16 gather, fp32 accumulate)
    {
        long tcount = (long)M * 32;
        agg_kernel<<<(int)((tcount + 255) / 256), 256>>>(M);
    }

    // 6. H = relu( relu(AGG + b_gcn) @ W1^T + b1 )
    gemm_hmma<true, true, false><<<ggrid, 256, SM_TOT>>>(
        AGG, W1h, W1l, b_gcn, b1, H, nullptr, M, ntiles);

    // 7. out
    {
        long tcount = (long)M * 32;
        final_kernel<<<(int)((tcount + 255) / 256), 256>>>(W2, b2, out, M);
    }
}

// round 6
// speedup vs baseline: 4.0561x; 1.1973x over previous
#include <cuda_runtime.h>
#include <cuda_bf16.h>
#include <cuda_fp16.h>
#include <cstdint>

#define NMAX 100000
#define EMAX 3200000
#define C 256

__device__ __half g_H16[(size_t)NMAX * C];    // GEMM1 output (fp16, agg source)
__device__ __half g_AGG16[(size_t)NMAX * C];  // agg output (fp16, GEMM2 input)
__device__ float g_dotp[(size_t)NMAX * 4];    // fused final partial dots
__device__ int   g_deg[NMAX];
__device__ float g_dinv[NMAX];
__device__ int   g_off[NMAX + 1];
__device__ int   g_cursor[NMAX];
__device__ int   g_src[EMAX];
__device__ int   g_bsum[128];
__device__ int   g_bpre[128];
__device__ int   g_idx64;

// bf16 hi/lo transposed+swizzled weight images
__device__ uint32_t g_W0h[2 * 16384];
__device__ uint32_t g_W0l[2 * 16384];
__device__ uint32_t g_W1h[2 * 16384];
__device__ uint32_t g_W1l[2 * 16384];

// ---------------------------------------------------------------------------
// helpers
// ---------------------------------------------------------------------------
__device__ __forceinline__ uint32_t smem_u32(const void* p) {
    uint32_t a;
    asm("{ .reg .u64 t; cvta.to.shared.u64 t, %1; cvt.u32.u64 %0, t; }" : "=r"(a) : "l"(p));
    return a;
}
__device__ __forceinline__ void ldsm_x4(uint32_t* r, uint32_t addr) {
    asm volatile("ldmatrix.sync.aligned.m8n8.x4.shared.b16 {%0,%1,%2,%3}, [%4];"
                 : "=r"(r[0]), "=r"(r[1]), "=r"(r[2]), "=r"(r[3]) : "r"(addr));
}
__device__ __forceinline__ void ldsm_x4_t(uint32_t* r, uint32_t addr) {
    asm volatile("ldmatrix.sync.aligned.m8n8.x4.trans.shared.b16 {%0,%1,%2,%3}, [%4];"
                 : "=r"(r[0]), "=r"(r[1]), "=r"(r[2]), "=r"(r[3]) : "r"(addr));
}
__device__ __forceinline__ void mma_bf16(float* d, const uint32_t* a, const uint32_t* b) {
    asm volatile(
        "mma.sync.aligned.m16n8k16.row.col.f32.bf16.bf16.f32 "
        "{%0,%1,%2,%3}, {%4,%5,%6,%7}, {%8,%9}, {%0,%1,%2,%3};"
        : "+f"(d[0]), "+f"(d[1]), "+f"(d[2]), "+f"(d[3])
        : "r"(a[0]), "r"(a[1]), "r"(a[2]), "r"(a[3]), "r"(b[0]), "r"(b[1]));
}
__device__ __forceinline__ void split_pair(float a, float b, uint32_t& hi, uint32_t& lo) {
    asm("cvt.rn.bf16x2.f32 %0, %1, %2;" : "=r"(hi) : "f"(b), "f"(a));
    float ha = __uint_as_float(hi << 16);
    float hb = __uint_as_float(hi & 0xFFFF0000u);
    float la = a - ha;
    float lb = b - hb;
    asm("cvt.rn.bf16x2.f32 %0, %1, %2;" : "=r"(lo) : "f"(lb), "f"(la));
}

// ---------------------------------------------------------------------------
// edge-index dtype detection
// ---------------------------------------------------------------------------
__global__ void detect_kernel(const void* ei, long n_slots) {
    const int* w = (const int*)ei;
    int tid = threadIdx.x;
    int any = 0;
    long n = n_slots < 2048 ? n_slots : 2048;
    for (long i = tid; i < n; i += blockDim.x)
        if (w[2 * i + 1] != 0) any = 1;
    any = __syncthreads_or(any);
    if (tid == 0) g_idx64 = any ? 0 : 1;
}
__device__ __forceinline__ long fetch_idx(const void* ei, long pos) {
    if (g_idx64) return (long)((const long long*)ei)[pos];
    return (long)((const int*)ei)[pos];
}

// ---------------------------------------------------------------------------
// degree / dinv / CSR build
// ---------------------------------------------------------------------------
__global__ void zero_deg(int M) {
    int i = blockIdx.x * blockDim.x + threadIdx.x;
    if (i < M) g_deg[i] = 0;
}
__global__ void count_deg(const void* ei, long E) {
    long e = (long)blockIdx.x * blockDim.x + threadIdx.x;
    if (e < E) atomicAdd(&g_deg[fetch_idx(ei, E + e)], 1);
}
__global__ void dinv_kernel(int M) {
    int i = blockIdx.x * blockDim.x + threadIdx.x;
    if (i < M) g_dinv[i] = rsqrtf((float)(g_deg[i] + 1));
}
__global__ void scan_phase1(int M) {
    __shared__ int s[1024];
    int tid = threadIdx.x;
    int i = blockIdx.x * 1024 + tid;
    s[tid] = (i < M) ? g_deg[i] : 0;
    __syncthreads();
    for (int d = 512; d > 0; d >>= 1) {
        if (tid < d) s[tid] += s[tid + d];
        __syncthreads();
    }
    if (tid == 0) g_bsum[blockIdx.x] = s[0];
}
__global__ void scan_phase2(int nb, int M, int Etot) {
    __shared__ int s[128];
    int tid = threadIdx.x;
    int v = (tid < nb) ? g_bsum[tid] : 0;
    s[tid] = v;
    __syncthreads();
    for (int d = 1; d < 128; d <<= 1) {
        int t = (tid >= d) ? s[tid - d] : 0;
        __syncthreads();
        s[tid] += t;
        __syncthreads();
    }
    if (tid < nb) g_bpre[tid] = s[tid] - v;
    if (tid == 0) g_off[M] = Etot;
}
__global__ void scan_phase3(int M) {
    __shared__ int s[1024];
    int tid = threadIdx.x;
    int i = blockIdx.x * 1024 + tid;
    int v = (i < M) ? g_deg[i] : 0;
    s[tid] = v;
    __syncthreads();
    for (int d = 1; d < 1024; d <<= 1) {
        int t = (tid >= d) ? s[tid - d] : 0;
        __syncthreads();
        s[tid] += t;
        __syncthreads();
    }
    if (i < M) {
        int excl = s[tid] - v + g_bpre[blockIdx.x];
        g_off[i] = excl;
        g_cursor[i] = excl;
    }
}
__global__ void fill_csr(const void* ei, long E) {
    long e = (long)blockIdx.x * blockDim.x + threadIdx.x;
    if (e < E) {
        int row = (int)fetch_idx(ei, e);
        int col = (int)fetch_idx(ei, E + e);
        g_src[atomicAdd(&g_cursor[col], 1)] = row;
    }
}

// ---------------------------------------------------------------------------
// CSR aggregation fp16 -> fp16, one warp per node, 4-edge unroll.
// ---------------------------------------------------------------------------
__device__ __forceinline__ void h8_fma(uint4 v, float nm, float* acc) {
    float2 f;
    f = __half22float2(*(const __half2*)&v.x);
    acc[0] = fmaf(f.x, nm, acc[0]); acc[1] = fmaf(f.y, nm, acc[1]);
    f = __half22float2(*(const __half2*)&v.y);
    acc[2] = fmaf(f.x, nm, acc[2]); acc[3] = fmaf(f.y, nm, acc[3]);
    f = __half22float2(*(const __half2*)&v.z);
    acc[4] = fmaf(f.x, nm, acc[4]); acc[5] = fmaf(f.y, nm, acc[5]);
    f = __half22float2(*(const __half2*)&v.w);
    acc[6] = fmaf(f.x, nm, acc[6]); acc[7] = fmaf(f.y, nm, acc[7]);
}

__global__ void agg_kernel(int M) {
    long gt = (long)blockIdx.x * blockDim.x + threadIdx.x;
    int n = (int)(gt >> 5);
    int lane = (int)(gt & 31);
    if (n >= M) return;

    const uint4* H16 = (const uint4*)g_H16;
    float dn = g_dinv[n];
    float acc[8] = {};

    h8_fma(H16[(long)n * 32 + lane], dn * dn, acc);

    int i = g_off[n];
    int end = g_off[n + 1];
    for (; i + 3 < end; i += 4) {
        int r0 = g_src[i], r1 = g_src[i + 1], r2 = g_src[i + 2], r3 = g_src[i + 3];
        float nm0 = dn * g_dinv[r0];
        float nm1 = dn * g_dinv[r1];
        float nm2 = dn * g_dinv[r2];
        float nm3 = dn * g_dinv[r3];
        uint4 v0 = H16[(long)r0 * 32 + lane];
        uint4 v1 = H16[(long)r1 * 32 + lane];
        uint4 v2 = H16[(long)r2 * 32 + lane];
        uint4 v3 = H16[(long)r3 * 32 + lane];
        h8_fma(v0, nm0, acc);
        h8_fma(v1, nm1, acc);
        h8_fma(v2, nm2, acc);
        h8_fma(v3, nm3, acc);
    }
    for (; i < end; i++) {
        int r0 = g_src[i];
        h8_fma(H16[(long)r0 * 32 + lane], dn * g_dinv[r0], acc);
    }

    uint4 o;
    __half2 h;
    h = __float22half2_rn(make_float2(acc[0], acc[1])); o.x = *(uint32_t*)&h;
    h = __float22half2_rn(make_float2(acc[2], acc[3])); o.y = *(uint32_t*)&h;
    h = __float22half2_rn(make_float2(acc[4], acc[5])); o.z = *(uint32_t*)&h;
    h = __float22half2_rn(make_float2(acc[6], acc[7])); o.w = *(uint32_t*)&h;
    ((uint4*)g_AGG16)[(long)n * 32 + lane] = o;
}

// ---------------------------------------------------------------------------
// Weight prep
// ---------------------------------------------------------------------------
__global__ void prep_weights(const float* __restrict__ W,
                             uint32_t* __restrict__ img_h, uint32_t* __restrict__ img_l) {
    int idx = blockIdx.x * blockDim.x + threadIdx.x;
    if (idx >= 32768) return;
    int tile = idx >> 14;
    int k = (idx >> 6) & 255;
    int np = idx & 63;
    int n = np * 2;
    int gn = tile * 128 + n;
    float a = W[gn * 256 + k];
    float b = W[(gn + 1) * 256 + k];
    uint32_t hi, lo;
    split_pair(a, b, hi, lo);
    uint32_t boff = (uint32_t)k * 256 + ((((n >> 3) ^ (k & 7)) << 4) | ((n & 7) * 2));
    img_h[tile * 16384 + (boff >> 2)] = hi;
    img_l[tile * 16384 + (boff >> 2)] = lo;
}

// ---------------------------------------------------------------------------
// HMMA GEMM, 3x bf16 split, persistent. IN16: fp16 A. OUT16: fp16 out.
// FUSED: epilogue computes partial dot with W2 -> g_dotp (no matrix store).
// ---------------------------------------------------------------------------
#define SM_BHI 0
#define SM_BLO 65536
#define SM_AHI 131072
#define SM_ALO 147456
#define SM_TOT 163840

template <bool PRE, bool POST, bool IN16, bool OUT16, bool FUSED>
__global__ void __launch_bounds__(256, 1)
gemm_hmma(const void* __restrict__ Avoid,
          const uint32_t* __restrict__ img_h, const uint32_t* __restrict__ img_l,
          const float* __restrict__ bpre, const float* __restrict__ bpost,
          __half* __restrict__ Out16, const float* __restrict__ W2,
          float* __restrict__ dotp, int M, int ntiles) {
    extern __shared__ char smem[];
    const uint32_t sb = smem_u32(smem);
    const int tid = threadIdx.x;
    const int lane = tid & 31;
    const int wid = tid >> 5;
    const int wm = wid & 3;
    const int wn = wid >> 2;
    const int n0 = blockIdx.y * 128;

    const float* Af = (const float*)Avoid;
    const __half* Ah16 = (const __half*)Avoid;

    // ---- copy B images ----
    {
        const uint4* sh = (const uint4*)(img_h + blockIdx.y * 16384);
        const uint4* sl = (const uint4*)(img_l + blockIdx.y * 16384);
        uint4* dh = (uint4*)(smem + SM_BHI);
        uint4* dl = (uint4*)(smem + SM_BLO);
#pragma unroll
        for (int i = 0; i < 16; i++) {
            dh[tid + i * 256] = sh[tid + i * 256];
            dl[tid + i * 256] = sl[tid + i * 256];
        }
    }

    const int frow = tid >> 1;
    const int fkh = (tid & 1) * 32;

    float4 pf[8];
    uint4 pf16[4];
    int t = blockIdx.x;
    {
        bool ok = (t < ntiles) && (t * 128 + frow < M);
        if (IN16) {
            const uint4* Ab = (const uint4*)(Ah16 + (long)(t * 128 + frow) * 256 + fkh);
#pragma unroll
            for (int j = 0; j < 4; j++)
                pf16[j] = ok ? Ab[j] : make_uint4(0, 0, 0, 0);
        } else {
            const float* Ab = Af + (long)(t * 128 + frow) * 256 + fkh;
#pragma unroll
            for (int j = 0; j < 8; j++)
                pf[j] = ok ? *(const float4*)(Ab + j * 4) : make_float4(0.f, 0.f, 0.f, 0.f);
        }
    }

    const int g = lane >> 3;

    for (; t < ntiles; t += 74) {
        const int m0 = t * 128;
        float acc[2][8][4];
#pragma unroll
        for (int a_ = 0; a_ < 2; a_++)
#pragma unroll
            for (int b_ = 0; b_ < 8; b_++)
#pragma unroll
                for (int c_ = 0; c_ < 4; c_++) acc[a_][b_][c_] = 0.f;

        for (int ch = 0; ch < 4; ch++) {
            // ---- convert prefetched chunk -> A smem (hi/lo bf16, swizzled) ----
            {
                uint32_t base_h = sb + SM_AHI + frow * 128;
                uint32_t base_l = sb + SM_ALO + frow * 128;
                if (IN16) {
#pragma unroll
                    for (int j = 0; j < 4; j++) {
                        uint4 q = pf16[j];
                        float2 f0 = __half22float2(*(const __half2*)&q.x);
                        float2 f1 = __half22float2(*(const __half2*)&q.y);
                        float2 f2 = __half22float2(*(const __half2*)&q.z);
                        float2 f3 = __half22float2(*(const __half2*)&q.w);
                        if (PRE) {
                            const float4 b0 = *(const float4*)(bpre + ch * 64 + fkh + j * 8);
                            const float4 b1 = *(const float4*)(bpre + ch * 64 + fkh + j * 8 + 4);
                            f0.x = fmaxf(f0.x + b0.x, 0.f); f0.y = fmaxf(f0.y + b0.y, 0.f);
                            f1.x = fmaxf(f1.x + b0.z, 0.f); f1.y = fmaxf(f1.y + b0.w, 0.f);
                            f2.x = fmaxf(f2.x + b1.x, 0.f); f2.y = fmaxf(f2.y + b1.y, 0.f);
                            f3.x = fmaxf(f3.x + b1.z, 0.f); f3.y = fmaxf(f3.y + b1.w, 0.f);
                        }
                        uint32_t h0, l0, h1, l1, h2, l2, h3, l3;
                        split_pair(f0.x, f0.y, h0, l0);
                        split_pair(f1.x, f1.y, h1, l1);
                        split_pair(f2.x, f2.y, h2, l2);
                        split_pair(f3.x, f3.y, h3, l3);
                        int kk = fkh + j * 8;
                        uint32_t off0 = ((((kk >> 3) ^ (frow & 7)) << 4));
                        asm volatile("st.shared.v2.b32 [%0], {%1, %2};"
                                     :: "r"(base_h + off0), "r"(h0), "r"(h1) : "memory");
                        asm volatile("st.shared.v2.b32 [%0], {%1, %2};"
                                     :: "r"(base_l + off0), "r"(l0), "r"(l1) : "memory");
                        asm volatile("st.shared.v2.b32 [%0], {%1, %2};"
                                     :: "r"(base_h + off0 + 8), "r"(h2), "r"(h3) : "memory");
                        asm volatile("st.shared.v2.b32 [%0], {%1, %2};"
                                     :: "r"(base_l + off0 + 8), "r"(l2), "r"(l3) : "memory");
                    }
                } else {
#pragma unroll
                    for (int j = 0; j < 8; j++) {
                        float4 v = pf[j];
                        if (PRE) {
                            const float4 bb = *(const float4*)(bpre + ch * 64 + fkh + j * 4);
                            v.x = fmaxf(v.x + bb.x, 0.f);
                            v.y = fmaxf(v.y + bb.y, 0.f);
                            v.z = fmaxf(v.z + bb.z, 0.f);
                            v.w = fmaxf(v.w + bb.w, 0.f);
                        }
                        uint32_t h0, l0, h1, l1;
                        split_pair(v.x, v.y, h0, l0);
                        split_pair(v.z, v.w, h1, l1);
                        int kk = fkh + j * 4;
                        uint32_t off = ((((kk >> 3) ^ (frow & 7)) << 4) | ((kk & 7) * 2));
                        asm volatile("st.shared.v2.b32 [%0], {%1, %2};"
                                     :: "r"(base_h + off), "r"(h0), "r"(h1) : "memory");
                        asm volatile("st.shared.v2.b32 [%0], {%1, %2};"
                                     :: "r"(base_l + off), "r"(l0), "r"(l1) : "memory");
                    }
                }
            }
            __syncthreads();

            // ---- prefetch next chunk ----
            {
                int nc = ch + 1;
                int nt = t;
                if (nc == 4) { nc = 0; nt = t + 74; }
                if (nt < ntiles) {
                    bool ok = (nt * 128 + frow) < M;
                    if (IN16) {
                        const uint4* Ab = (const uint4*)(Ah16 + (long)(nt * 128 + frow) * 256 + nc * 64 + fkh);
#pragma unroll
                        for (int j = 0; j < 4; j++)
                            pf16[j] = ok ? Ab[j] : make_uint4(0, 0, 0, 0);
                    } else {
                        const float* Ab = Af + (long)(nt * 128 + frow) * 256 + nc * 64 + fkh;
#pragma unroll
                        for (int j = 0; j < 8; j++)
                            pf[j] = ok ? *(const float4*)(Ab + j * 4) : make_float4(0.f, 0.f, 0.f, 0.f);
                    }
                }
            }

            // ---- MMA over 4 k16 steps ----
#pragma unroll
            for (int ks = 0; ks < 4; ks++) {
                const int klocal = ks * 16;
                const int kglob = ch * 64 + klocal;

                uint32_t ah[2][4], al[2][4];
#pragma unroll
                for (int mf = 0; mf < 2; mf++) {
                    int m = wm * 32 + mf * 16 + ((g & 1) << 3) + (lane & 7);
                    int kc = klocal + ((g >> 1) << 3);
                    uint32_t off = (uint32_t)m * 128 + ((((kc >> 3) ^ (m & 7)) << 4));
                    ldsm_x4(ah[mf], sb + SM_AHI + off);
                    ldsm_x4(al[mf], sb + SM_ALO + off);
                }

                uint32_t bh[8][2], bl[8][2];
#pragma unroll
                for (int q = 0; q < 4; q++) {
                    int nb = wn * 64 + q * 16 + ((g >> 1) << 3);
                    int kr = kglob + ((g & 1) << 3) + (lane & 7);
                    uint32_t off = (uint32_t)kr * 256 + ((((nb >> 3) ^ (kr & 7)) << 4));
                    uint32_t r[4], s[4];
                    ldsm_x4_t(r, sb + SM_BHI + off);
                    ldsm_x4_t(s, sb + SM_BLO + off);
                    bh[q * 2][0] = r[0]; bh[q * 2][1] = r[1];
                    bh[q * 2 + 1][0] = r[2]; bh[q * 2 + 1][1] = r[3];
                    bl[q * 2][0] = s[0]; bl[q * 2][1] = s[1];
                    bl[q * 2 + 1][0] = s[2]; bl[q * 2 + 1][1] = s[3];
                }

#pragma unroll
                for (int mf = 0; mf < 2; mf++)
#pragma unroll
                    for (int nf = 0; nf < 8; nf++) {
                        mma_bf16(acc[mf][nf], ah[mf], bh[nf]);
                        mma_bf16(acc[mf][nf], ah[mf], bl[nf]);
                        mma_bf16(acc[mf][nf], al[mf], bh[nf]);
                    }
            }
            __syncthreads();
        }

        // ---- epilogue ----
#pragma unroll
        for (int mf = 0; mf < 2; mf++) {
#pragma unroll
            for (int half = 0; half < 2; half++) {
                int m = m0 + wm * 32 + mf * 16 + (lane >> 2) + half * 8;
                float dot = 0.f;
#pragma unroll
                for (int nf = 0; nf < 8; nf++) {
                    float2 v;
                    v.x = acc[mf][nf][half * 2];
                    v.y = acc[mf][nf][half * 2 + 1];
                    if (POST) {
                        const float2 bb = *(const float2*)(bpost + n0 + wn * 64 + nf * 8 + 2 * (lane & 3));
                        v.x = fmaxf(v.x + bb.x, 0.f);
                        v.y = fmaxf(v.y + bb.y, 0.f);
                    }
                    if (FUSED) {
                        const float2 w2v = *(const float2*)(W2 + n0 + wn * 64 + nf * 8 + 2 * (lane & 3));
                        dot = fmaf(v.x, w2v.x, dot);
                        dot = fmaf(v.y, w2v.y, dot);
                    } else if (OUT16) {
                        if (m < M) {
                            __half2 h = __float22half2_rn(v);
                            *(__half2*)(Out16 + (long)m * 256 + n0 + wn * 64 + nf * 8 + 2 * (lane & 3)) = h;
                        }
                    }
                }
                if (FUSED) {
                    dot += __shfl_xor_sync(0xFFFFFFFFu, dot, 1);
                    dot += __shfl_xor_sync(0xFFFFFFFFu, dot, 2);
                    if ((lane & 3) == 0 && m < M)
                        dotp[(long)m * 4 + blockIdx.y * 2 + wn] = dot;
                }
            }
        }
    }
}

// ---------------------------------------------------------------------------
// Final combine: out[m] = sigmoid(relu(sum of 4 partials + b2))
// ---------------------------------------------------------------------------
__global__ void final_combine(const float* __restrict__ b2, float* __restrict__ out, int M) {
    int m = blockIdx.x * blockDim.x + threadIdx.x;
    if (m < M) {
        float4 p = ((const float4*)g_dotp)[m];
        float v = fmaxf(p.x + p.y + p.z + p.w + b2[0], 0.f);
        out[m] = 1.f / (1.f + __expf(-v));
    }
}

// ---------------------------------------------------------------------------
extern "C" void kernel_launch(void* const* d_in, const int* in_sizes, int n_in,
                              void* d_out, int out_size) {
    const float* x     = (const float*)d_in[0];
    const void*  ei    = d_in[1];
    const float* W_gcn = (const float*)d_in[2];
    const float* b_gcn = (const float*)d_in[3];
    const float* W1    = (const float*)d_in[4];
    const float* b1    = (const float*)d_in[5];
    const float* W2    = (const float*)d_in[6];
    const float* b2    = (const float*)d_in[7];
    float* out = (float*)d_out;

    const int  M = in_sizes[0] / C;
    const long E = (long)in_sizes[1] / 2;
    const int ntiles = (M + 127) / 128;

    __half *H16, *AGG16;
    float* dotp;
    cudaGetSymbolAddress((void**)&H16, g_H16);
    cudaGetSymbolAddress((void**)&AGG16, g_AGG16);
    cudaGetSymbolAddress((void**)&dotp, g_dotp);
    uint32_t *W0h, *W0l, *W1h, *W1l;
    cudaGetSymbolAddress((void**)&W0h, g_W0h);
    cudaGetSymbolAddress((void**)&W0l, g_W0l);
    cudaGetSymbolAddress((void**)&W1h, g_W1h);
    cudaGetSymbolAddress((void**)&W1l, g_W1l);

    static cudaStream_t s1 = nullptr;
    static cudaEvent_t evFork = nullptr, evJoin = nullptr;
    if (!s1) {
        cudaStreamCreateWithFlags(&s1, cudaStreamNonBlocking);
        cudaEventCreateWithFlags(&evFork, cudaEventDisableTiming);
        cudaEventCreateWithFlags(&evJoin, cudaEventDisableTiming);
        cudaFuncSetAttribute(gemm_hmma<false, false, false, true, false>,
                             cudaFuncAttributeMaxDynamicSharedMemorySize, SM_TOT);
        cudaFuncSetAttribute(gemm_hmma<true, true, true, false, true>,
                             cudaFuncAttributeMaxDynamicSharedMemorySize, SM_TOT);
    }

    // ---- fork: stream 0 = CSR chain, s1 = weights + GEMM1 ----
    cudaEventRecord(evFork, 0);
    cudaStreamWaitEvent(s1, evFork, 0);

    // chain A (stream 0): detect -> deg -> dinv -> scan -> fill
    detect_kernel<<<1, 256>>>(ei, E);
    zero_deg<<<(M + 255) / 256, 256>>>(M);
    count_deg<<<(int)((E + 255) / 256), 256>>>(ei, E);
    dinv_kernel<<<(M + 255) / 256, 256>>>(M);
    int nb = (M + 1023) / 1024;
    scan_phase1<<<nb, 1024>>>(M);
    scan_phase2<<<1, 128>>>(nb, M, (int)E);
    scan_phase3<<<nb, 1024>>>(M);
    fill_csr<<<(int)((E + 255) / 256), 256>>>(ei, E);

    // chain B (s1): weight prep + GEMM1 (H16 = fp16(x @ W_gcn^T))
    prep_weights<<<128, 256, 0, s1>>>(W_gcn, W0h, W0l);
    prep_weights<<<128, 256, 0, s1>>>(W1, W1h, W1l);
    dim3 ggrid(74, 2);
    gemm_hmma<false, false, false, true, false><<<ggrid, 256, SM_TOT, s1>>>(
        x, W0h, W0l, nullptr, nullptr, H16, nullptr, nullptr, M, ntiles);

    // ---- join ----
    cudaEventRecord(evJoin, s1);
    cudaStreamWaitEvent(0, evJoin, 0);

    // agg: fp16 gather, fp32 accumulate, fp16 store
    {
        long tcount = (long)M * 32;
        agg_kernel<<<(int)((tcount + 255) / 256), 256>>>(M);
    }

    // GEMM2 fused: partial dots of relu(relu(AGG+b_gcn)@W1^T + b1) with W2
    gemm_hmma<true, true, true, false, true><<<ggrid, 256, SM_TOT>>>(
        AGG16, W1h, W1l, b_gcn, b1, nullptr, W2, dotp, M, ntiles);

    // combine + sigmoid
    final_combine<<<(M + 255) / 256, 256>>>(b2, out, M);
}